// round 2
// baseline (speedup 1.0000x reference)
#include <cuda_runtime.h>
#include <math.h>

#define NN 50000
#define NE 1600000
#define DD 256
#define HH 8
#define HDIM 32
#define EDIM 32
#define FF 1024

// ---------------- device scratch (static globals; no allocation) ----------------
__device__ float g_xn [(size_t)NN*DD];
__device__ float g_q  [(size_t)NN*DD];
__device__ float g_k  [(size_t)NN*DD];
__device__ float g_v  [(size_t)NN*DD];
__device__ float g_ep [(size_t)NE*HDIM];
__device__ float g_sc [(size_t)NE*HH];
__device__ float g_m  [(size_t)NN*HH];
__device__ float g_l  [(size_t)NN*HH];
__device__ float g_agg[(size_t)NN*DD];
__device__ float g_x1 [(size_t)NN*DD];
__device__ float g_xn2[(size_t)NN*DD];
__device__ float g_ff1[(size_t)NN*FF];
__device__ int   g_counts[NN];
__device__ int   g_rowptr[NN+1];
__device__ int   g_cursor[NN];
__device__ int   g_csr[NE];

static inline int ceildiv(int a, int b){ return (a + b - 1) / b; }

// ---------------- CSR build ----------------
__global__ void zero_counts_kernel(){
    int i = blockIdx.x*blockDim.x + threadIdx.x;
    if (i < NN) g_counts[i] = 0;
}

__global__ void hist_kernel(const int* __restrict__ dst){
    int e = blockIdx.x*blockDim.x + threadIdx.x;
    if (e < NE) atomicAdd(&g_counts[dst[e]], 1);
}

__global__ void scan_kernel(){
    __shared__ int sh[2][1024];
    __shared__ int carry;
    int t = threadIdx.x;
    if (t == 0){ carry = 0; g_rowptr[0] = 0; }
    __syncthreads();
    for (int base = 0; base < NN; base += 1024){
        int i = base + t;
        int val = (i < NN) ? g_counts[i] : 0;
        sh[0][t] = val;
        __syncthreads();
        int s = 0, d = 1;
        for (int off = 1; off < 1024; off <<= 1){
            int add = (t >= off) ? sh[s][t-off] : 0;
            sh[d][t] = sh[s][t] + add;
            __syncthreads();
            s ^= 1; d ^= 1;
        }
        int inc = sh[s][t] + carry;   // inclusive prefix + carry
        if (i < NN){ g_rowptr[i+1] = inc; g_cursor[i] = inc - val; }
        __syncthreads();
        if (t == 1023) carry = inc;
        __syncthreads();
    }
}

__global__ void scatter_kernel(const int* __restrict__ dst){
    int e = blockIdx.x*blockDim.x + threadIdx.x;
    if (e >= NE) return;
    int pos = atomicAdd(&g_cursor[dst[e]], 1);
    g_csr[pos] = e;
}

// ---------------- LayerNorm: one warp per row, D=256 (8 per lane) ----------------
__global__ void ln_kernel(const float* __restrict__ x, const float* __restrict__ g,
                          const float* __restrict__ b, float* __restrict__ out){
    int warp = (blockIdx.x*blockDim.x + threadIdx.x) >> 5;
    if (warp >= NN) return;
    int lane = threadIdx.x & 31;
    const float* row = x + (size_t)warp * DD;
    float vals[8];
    #pragma unroll
    for (int j = 0; j < 8; j++) vals[j] = row[j*32 + lane];
    float s = 0.f;
    #pragma unroll
    for (int j = 0; j < 8; j++) s += vals[j];
    #pragma unroll
    for (int o = 16; o; o >>= 1) s += __shfl_xor_sync(0xffffffffu, s, o);
    float mu = s * (1.0f/DD);
    float vs = 0.f;
    #pragma unroll
    for (int j = 0; j < 8; j++){ float d0 = vals[j]-mu; vs += d0*d0; }
    #pragma unroll
    for (int o = 16; o; o >>= 1) vs += __shfl_xor_sync(0xffffffffu, vs, o);
    float rstd = rsqrtf(vs*(1.0f/DD) + 1e-5f);
    float* orow = out + (size_t)warp * DD;
    #pragma unroll
    for (int j = 0; j < 8; j++){
        int c = j*32 + lane;
        orow[c] = (vals[j]-mu)*rstd*g[c] + b[c];
    }
}

// ---------------- SGEMM: C[M,N] = A[M,K] @ B[N,K]^T + bias, epilogues ----------------
#define EPI_BIAS 0
#define EPI_GELU 1
#define EPI_RES  2

template<int MODE>
__global__ __launch_bounds__(256)
void sgemm_kernel(int M, int N, int K,
                  const float* __restrict__ A, const float* __restrict__ B,
                  const float* __restrict__ bias,
                  const float* __restrict__ res, const float* __restrict__ scale,
                  float* __restrict__ C){
    const int BM = 128, BN = 128, BK = 16;
    __shared__ float As[BK][BM];
    __shared__ float Bs[BK][BN];
    int tid = threadIdx.x;
    int bn = blockIdx.x * BN;
    int bm = blockIdx.y * BM;
    int tx = (tid & 15) * 8;
    int ty = (tid >> 4) * 8;
    float acc[8][8] = {};
    int ldRow = tid >> 2;          // 0..63
    int ldCol = (tid & 3) * 4;     // 0,4,8,12

    for (int k0 = 0; k0 < K; k0 += BK){
        #pragma unroll
        for (int p = 0; p < 2; p++){
            int m = ldRow + p*64;
            int gm = bm + m;
            float4 t = make_float4(0.f,0.f,0.f,0.f);
            if (gm < M) t = *(const float4*)(A + (size_t)gm*K + k0 + ldCol);
            As[ldCol+0][m] = t.x; As[ldCol+1][m] = t.y;
            As[ldCol+2][m] = t.z; As[ldCol+3][m] = t.w;
        }
        #pragma unroll
        for (int p = 0; p < 2; p++){
            int nn = ldRow + p*64;
            float4 t = *(const float4*)(B + (size_t)(bn+nn)*K + k0 + ldCol);
            Bs[ldCol+0][nn] = t.x; Bs[ldCol+1][nn] = t.y;
            Bs[ldCol+2][nn] = t.z; Bs[ldCol+3][nn] = t.w;
        }
        __syncthreads();
        #pragma unroll
        for (int kk = 0; kk < BK; kk++){
            float rm[8], rn[8];
            #pragma unroll
            for (int i = 0; i < 8; i++) rm[i] = As[kk][ty+i];
            #pragma unroll
            for (int j = 0; j < 8; j++) rn[j] = Bs[kk][tx+j];
            #pragma unroll
            for (int i = 0; i < 8; i++)
                #pragma unroll
                for (int j = 0; j < 8; j++)
                    acc[i][j] = fmaf(rm[i], rn[j], acc[i][j]);
        }
        __syncthreads();
    }

    float sc = (MODE == EPI_RES) ? scale[0] : 0.f;
    #pragma unroll
    for (int i = 0; i < 8; i++){
        int gm = bm + ty + i;
        if (gm < M){
            #pragma unroll
            for (int j = 0; j < 8; j++){
                int gn = bn + tx + j;
                float v = acc[i][j] + bias[gn];
                if (MODE == EPI_GELU){
                    v = 0.5f * v * (1.0f + erff(v * 0.7071067811865475f));
                } else if (MODE == EPI_RES){
                    v = res[(size_t)gm*N + gn] + sc * v;
                }
                C[(size_t)gm*N + gn] = v;
            }
        }
    }
}

// ---------------- edge projection: ep = ef @ We^T + be (32x32), warp per edge ----------------
__global__ void ep_kernel(const float* __restrict__ ef, const float* __restrict__ We,
                          const float* __restrict__ be){
    __shared__ float Ws[EDIM][HDIM+1];  // Ws[j][d] = We[d][j]
    __shared__ float bs[HDIM];
    int tid = threadIdx.x;
    for (int i = tid; i < EDIM*HDIM; i += blockDim.x){
        int d = i >> 5, j = i & 31;
        Ws[j][d] = We[d*EDIM + j];
    }
    if (tid < HDIM) bs[tid] = be[tid];
    __syncthreads();
    int e = (blockIdx.x*blockDim.x + tid) >> 5;
    if (e >= NE) return;
    int lane = tid & 31;
    float myef = ef[(size_t)e*EDIM + lane];
    float acc = bs[lane];
    #pragma unroll
    for (int j = 0; j < EDIM; j++){
        float efj = __shfl_sync(0xffffffffu, myef, j);
        acc = fmaf(Ws[j][lane], efj, acc);
    }
    g_ep[(size_t)e*HDIM + lane] = acc;
}

// ---------------- attention pass 1: warp per dst node, online softmax ----------------
__global__ void attn1_kernel(const int* __restrict__ src, const float* __restrict__ ew){
    int node = (blockIdx.x*blockDim.x + threadIdx.x) >> 5;
    if (node >= NN) return;
    int lane = threadIdx.x & 31;
    const float* qrow = g_q + (size_t)node*DD;
    float qr[HH];
    #pragma unroll
    for (int h = 0; h < HH; h++) qr[h] = qrow[h*32 + lane];
    float m[HH], l[HH], acc[HH];
    #pragma unroll
    for (int h = 0; h < HH; h++){ m[h] = -INFINITY; l[h] = 0.f; acc[h] = 0.f; }
    int s0 = g_rowptr[node], s1 = g_rowptr[node+1];
    for (int j = s0; j < s1; j++){
        int e = g_csr[j];
        int s = src[e];
        float epl = g_ep[(size_t)e*HDIM + lane];
        float w = ew[e];
        const float* krow = g_k + (size_t)s*DD;
        const float* vrow = g_v + (size_t)s*DD;
        float sc[HH];
        #pragma unroll
        for (int h = 0; h < HH; h++) sc[h] = qr[h] * (krow[h*32 + lane] + epl);
        #pragma unroll
        for (int o = 16; o; o >>= 1){
            #pragma unroll
            for (int h = 0; h < HH; h++) sc[h] += __shfl_xor_sync(0xffffffffu, sc[h], o);
        }
        #pragma unroll
        for (int h = 0; h < HH; h++) sc[h] *= 0.17677669529663688f * w;  // HD^-0.5 * ew
        if (lane < HH) g_sc[(size_t)e*HH + lane] = sc[lane];
        #pragma unroll
        for (int h = 0; h < HH; h++){
            float nm = fmaxf(m[h], sc[h]);
            float c  = expf(m[h] - nm);
            float p  = expf(sc[h] - nm);
            l[h]   = l[h]*c + p;
            acc[h] = acc[h]*c + p * vrow[h*32 + lane];
            m[h]   = nm;
        }
    }
    float* arow = g_agg + (size_t)node*DD;
    #pragma unroll
    for (int h = 0; h < HH; h++){
        float inv = (l[h] > 0.f) ? 1.f/l[h] : 0.f;
        arow[h*32 + lane] = acc[h] * inv;
    }
    if (lane < HH){ g_m[node*HH + lane] = m[lane]; g_l[node*HH + lane] = l[lane]; }
}

// ---------------- attention pass 2: per-edge attn_weights ----------------
__global__ void attn2_kernel(const int* __restrict__ dst, float* __restrict__ out_attn){
    int i = blockIdx.x*blockDim.x + threadIdx.x;
    if (i >= NE*HH) return;
    int e = i >> 3, h = i & 7;
    int d = dst[e];
    float mm = g_m[d*HH + h];
    float ll = g_l[d*HH + h];
    out_attn[i] = expf(g_sc[i] - mm) / ll;
}

// ---------------- launch ----------------
extern "C" void kernel_launch(void* const* d_in, const int* in_sizes, int n_in,
                              void* d_out, int out_size){
    const float* x   = (const float*)d_in[0];
    const int*   ei  = (const int*)  d_in[1];
    const int*   src = ei;
    const int*   dst = ei + NE;
    const float* ef  = (const float*)d_in[2];
    const float* ew  = (const float*)d_in[3];
    const float* Wq  = (const float*)d_in[4];  const float* bq = (const float*)d_in[5];
    const float* Wk  = (const float*)d_in[6];  const float* bk = (const float*)d_in[7];
    const float* Wv  = (const float*)d_in[8];  const float* bv = (const float*)d_in[9];
    const float* We  = (const float*)d_in[10]; const float* be = (const float*)d_in[11];
    const float* Wo  = (const float*)d_in[12]; const float* bo = (const float*)d_in[13];
    const float* W1  = (const float*)d_in[14]; const float* b1 = (const float*)d_in[15];
    const float* W2  = (const float*)d_in[16]; const float* b2 = (const float*)d_in[17];
    const float* g1  = (const float*)d_in[18]; const float* be1 = (const float*)d_in[19];
    const float* g2  = (const float*)d_in[20]; const float* be2 = (const float*)d_in[21];
    const float* alpha = (const float*)d_in[22];
    const float* beta  = (const float*)d_in[23];

    float* out_x = (float*)d_out;
    // second tuple output (attn_weights) follows x when the harness allocated room for it
    float* out_attn = ((size_t)out_size >= (size_t)NN*DD + (size_t)NE*HH)
                      ? out_x + (size_t)NN*DD : nullptr;

    void *p_xn, *p_q, *p_k, *p_v, *p_agg, *p_x1, *p_xn2, *p_ff1;
    cudaGetSymbolAddress(&p_xn,  g_xn);
    cudaGetSymbolAddress(&p_q,   g_q);
    cudaGetSymbolAddress(&p_k,   g_k);
    cudaGetSymbolAddress(&p_v,   g_v);
    cudaGetSymbolAddress(&p_agg, g_agg);
    cudaGetSymbolAddress(&p_x1,  g_x1);
    cudaGetSymbolAddress(&p_xn2, g_xn2);
    cudaGetSymbolAddress(&p_ff1, g_ff1);

    // --- CSR by dst ---
    zero_counts_kernel<<<ceildiv(NN,256), 256>>>();
    hist_kernel<<<ceildiv(NE,256), 256>>>(dst);
    scan_kernel<<<1, 1024>>>();
    scatter_kernel<<<ceildiv(NE,256), 256>>>(dst);

    // --- pre-norm + QKV ---
    ln_kernel<<<ceildiv(NN,8), 256>>>(x, g1, be1, (float*)p_xn);
    dim3 gQ(DD/128, ceildiv(NN,128));
    sgemm_kernel<EPI_BIAS><<<gQ,256>>>(NN, DD, DD, (const float*)p_xn, Wq, bq, nullptr, nullptr, (float*)p_q);
    sgemm_kernel<EPI_BIAS><<<gQ,256>>>(NN, DD, DD, (const float*)p_xn, Wk, bk, nullptr, nullptr, (float*)p_k);
    sgemm_kernel<EPI_BIAS><<<gQ,256>>>(NN, DD, DD, (const float*)p_xn, Wv, bv, nullptr, nullptr, (float*)p_v);

    // --- edge projection ---
    ep_kernel<<<ceildiv(NE,8), 256>>>(ef, We, be);

    // --- attention: scores + online softmax + aggregate, then weights ---
    attn1_kernel<<<ceildiv(NN,8), 256>>>(src, ew);
    if (out_attn)
        attn2_kernel<<<ceildiv(NE*HH,256), 256>>>(dst, out_attn);

    // --- output projection + residual (x1 = x + alpha * (agg@Wo^T + bo)) ---
    sgemm_kernel<EPI_RES><<<gQ,256>>>(NN, DD, DD, (const float*)p_agg, Wo, bo, x, alpha, (float*)p_x1);

    // --- FFN ---
    ln_kernel<<<ceildiv(NN,8), 256>>>((const float*)p_x1, g2, be2, (float*)p_xn2);
    dim3 gF1(FF/128, ceildiv(NN,128));
    sgemm_kernel<EPI_GELU><<<gF1,256>>>(NN, FF, DD, (const float*)p_xn2, W1, b1, nullptr, nullptr, (float*)p_ff1);
    sgemm_kernel<EPI_RES><<<gQ,256>>>(NN, DD, FF, (const float*)p_ff1, W2, b2, (const float*)p_x1, beta, out_x);
}

// round 11
// speedup vs baseline: 1.2546x; 1.2546x over previous
#include <cuda_runtime.h>
#include <cuda_bf16.h>
#include <math.h>
#include <stdint.h>

#define NN 50000
#define NE 1600000
#define DD 256
#define HH 8
#define HDIM 32
#define EDIM 32
#define FF 1024

// ---------------- device scratch (static globals; no allocation) ----------------
__device__ float g_xn [(size_t)NN*DD];
__device__ float g_q  [(size_t)NN*DD];
__device__ float g_k  [(size_t)NN*DD];
__device__ float g_v  [(size_t)NN*DD];
__device__ float g_ep [(size_t)NE*HDIM];
__device__ float g_sc [(size_t)NE*HH];
__device__ float g_m  [(size_t)NN*HH];
__device__ float g_l  [(size_t)NN*HH];
__device__ float g_agg[(size_t)NN*DD];
__device__ float g_x1 [(size_t)NN*DD];
__device__ float g_xn2[(size_t)NN*DD];
__device__ float g_ff1[(size_t)NN*FF];
__device__ int   g_counts[NN];
__device__ int   g_rowptr[NN+1];
__device__ int   g_cursor[NN];
__device__ int   g_csr[NE];

static inline int ceildiv(int a, int b){ return (a + b - 1) / b; }

// ---------------- bf16 split helpers ----------------
__device__ __forceinline__ void bf16_split4(float4 v, uint2& hi, uint2& lo){
    __nv_bfloat16 h0 = __float2bfloat16_rn(v.x);
    __nv_bfloat16 h1 = __float2bfloat16_rn(v.y);
    __nv_bfloat16 h2 = __float2bfloat16_rn(v.z);
    __nv_bfloat16 h3 = __float2bfloat16_rn(v.w);
    __nv_bfloat16 l0 = __float2bfloat16_rn(v.x - __bfloat162float(h0));
    __nv_bfloat16 l1 = __float2bfloat16_rn(v.y - __bfloat162float(h1));
    __nv_bfloat16 l2 = __float2bfloat16_rn(v.z - __bfloat162float(h2));
    __nv_bfloat16 l3 = __float2bfloat16_rn(v.w - __bfloat162float(h3));
    hi.x = ((uint32_t)__bfloat16_as_ushort(h1) << 16) | __bfloat16_as_ushort(h0);
    hi.y = ((uint32_t)__bfloat16_as_ushort(h3) << 16) | __bfloat16_as_ushort(h2);
    lo.x = ((uint32_t)__bfloat16_as_ushort(l1) << 16) | __bfloat16_as_ushort(l0);
    lo.y = ((uint32_t)__bfloat16_as_ushort(l3) << 16) | __bfloat16_as_ushort(l2);
}

// mma.sync m16n8k16 row.col f32.bf16.bf16.f32 — base-target PTX (sm_80+)
__device__ __forceinline__ void mma16816(float* c,
        uint32_t a0, uint32_t a1, uint32_t a2, uint32_t a3,
        uint32_t b0, uint32_t b1){
    asm volatile("mma.sync.aligned.m16n8k16.row.col.f32.bf16.bf16.f32 "
        "{%0,%1,%2,%3}, {%4,%5,%6,%7}, {%8,%9}, {%0,%1,%2,%3};"
        : "+f"(c[0]), "+f"(c[1]), "+f"(c[2]), "+f"(c[3])
        : "r"(a0), "r"(a1), "r"(a2), "r"(a3), "r"(b0), "r"(b1));
}

// ---------------- CSR build ----------------
__global__ void zero_counts_kernel(){
    int i = blockIdx.x*blockDim.x + threadIdx.x;
    if (i < NN) g_counts[i] = 0;
}
__global__ void hist_kernel(const int* __restrict__ dst){
    int e = blockIdx.x*blockDim.x + threadIdx.x;
    if (e < NE) atomicAdd(&g_counts[dst[e]], 1);
}
__global__ void scan_kernel(){
    __shared__ int sh[2][1024];
    __shared__ int carry;
    int t = threadIdx.x;
    if (t == 0){ carry = 0; g_rowptr[0] = 0; }
    __syncthreads();
    for (int base = 0; base < NN; base += 1024){
        int i = base + t;
        int val = (i < NN) ? g_counts[i] : 0;
        sh[0][t] = val;
        __syncthreads();
        int s = 0, d = 1;
        for (int off = 1; off < 1024; off <<= 1){
            int add = (t >= off) ? sh[s][t-off] : 0;
            sh[d][t] = sh[s][t] + add;
            __syncthreads();
            s ^= 1; d ^= 1;
        }
        int inc = sh[s][t] + carry;
        if (i < NN){ g_rowptr[i+1] = inc; g_cursor[i] = inc - val; }
        __syncthreads();
        if (t == 1023) carry = inc;
        __syncthreads();
    }
}
__global__ void scatter_kernel(const int* __restrict__ dst){
    int e = blockIdx.x*blockDim.x + threadIdx.x;
    if (e >= NE) return;
    int pos = atomicAdd(&g_cursor[dst[e]], 1);
    g_csr[pos] = e;
}

// ---------------- LayerNorm ----------------
__global__ void ln_kernel(const float* __restrict__ x, const float* __restrict__ g,
                          const float* __restrict__ b, float* __restrict__ out){
    int warp = (blockIdx.x*blockDim.x + threadIdx.x) >> 5;
    if (warp >= NN) return;
    int lane = threadIdx.x & 31;
    const float* row = x + (size_t)warp * DD;
    float vals[8];
    #pragma unroll
    for (int j = 0; j < 8; j++) vals[j] = row[j*32 + lane];
    float s = 0.f;
    #pragma unroll
    for (int j = 0; j < 8; j++) s += vals[j];
    #pragma unroll
    for (int o = 16; o; o >>= 1) s += __shfl_xor_sync(0xffffffffu, s, o);
    float mu = s * (1.0f/DD);
    float vs = 0.f;
    #pragma unroll
    for (int j = 0; j < 8; j++){ float d0 = vals[j]-mu; vs += d0*d0; }
    #pragma unroll
    for (int o = 16; o; o >>= 1) vs += __shfl_xor_sync(0xffffffffu, vs, o);
    float rstd = rsqrtf(vs*(1.0f/DD) + 1e-5f);
    float* orow = out + (size_t)warp * DD;
    #pragma unroll
    for (int j = 0; j < 8; j++){
        int c = j*32 + lane;
        orow[c] = (vals[j]-mu)*rstd*g[c] + b[c];
    }
}

// ---------------- 3xBF16 warp-MMA GEMM: C[M,N] = A[M,K] @ B[N,K]^T + bias ----------------
// A = Ah + Al, B = Bh + Bl (bf16 splits). D += Ah@Bh + Ah@Bl + Al@Bh (fp32 accum)
#define EPI_BIAS 0
#define EPI_GELU 1
#define EPI_RES  2

#define BKC 32      // K elements per chunk
#define ROWB 80     // padded SMEM row bytes: 32*2 + 16 (bank-conflict-free fragments)

template<int MODE>
__global__ __launch_bounds__(256)
void mma_gemm_kernel(int M, int N, int K,
                     const float* __restrict__ A, const float* __restrict__ B,
                     const float* __restrict__ bias,
                     const float* __restrict__ res, const float* __restrict__ scale,
                     float* __restrict__ C){
    __shared__ char sAh[128*ROWB];
    __shared__ char sAl[128*ROWB];
    __shared__ char sBh[128*ROWB];
    __shared__ char sBl[128*ROWB];
    int tid = threadIdx.x;
    int wid = tid >> 5, lane = tid & 31;
    int g = lane >> 2, tig = lane & 3;
    int warp_m = wid & 1, warp_n = wid >> 1;   // 2 x 4 warp grid: warp tile 64 x 32
    int bm = blockIdx.y * 128, bn = blockIdx.x * 128;

    float acc[4][4][4] = {};   // [mt][nt][c0..c3]

    int NC = K / BKC;
    for (int kc = 0; kc < NC; kc++){
        int k0g = kc * BKC;
        // load chunk: A/B 128 rows x 32 floats -> hi/lo bf16 (1024 float4, 4 per thread)
        #pragma unroll
        for (int it = 0; it < 4; it++){
            int idx = tid + it*256;
            int row = idx >> 3, fi = idx & 7;
            uint32_t off = (uint32_t)(row*ROWB + fi*8);
            int gm = bm + row;
            float4 va = make_float4(0.f,0.f,0.f,0.f);
            if (gm < M) va = *(const float4*)(A + (size_t)gm*K + k0g + fi*4);
            uint2 vh, vl;
            bf16_split4(va, vh, vl);
            *(uint2*)(sAh + off) = vh;
            *(uint2*)(sAl + off) = vl;
            float4 vb = *(const float4*)(B + (size_t)(bn + row)*K + k0g + fi*4);
            bf16_split4(vb, vh, vl);
            *(uint2*)(sBh + off) = vh;
            *(uint2*)(sBl + off) = vl;
        }
        __syncthreads();
        #pragma unroll
        for (int ks = 0; ks < 2; ks++){
            int k0 = ks*16;
            // B fragments (col-major k16n8): b0 = (k0+tig*2, n), b1 = (k0+8+tig*2, n)
            uint32_t bh[4][2], bl[4][2];
            #pragma unroll
            for (int nt = 0; nt < 4; nt++){
                int n = warp_n*32 + nt*8 + g;
                uint32_t o0 = (uint32_t)(n*ROWB + (k0 + tig*2)*2);
                uint32_t o1 = (uint32_t)(n*ROWB + (k0 + 8 + tig*2)*2);
                bh[nt][0] = *(const uint32_t*)(sBh + o0);
                bh[nt][1] = *(const uint32_t*)(sBh + o1);
                bl[nt][0] = *(const uint32_t*)(sBl + o0);
                bl[nt][1] = *(const uint32_t*)(sBl + o1);
            }
            #pragma unroll
            for (int mt = 0; mt < 4; mt++){
                int r0 = warp_m*64 + mt*16 + g;
                uint32_t o00 = (uint32_t)( r0   *ROWB + (k0 + tig*2)*2);
                uint32_t o10 = (uint32_t)((r0+8)*ROWB + (k0 + tig*2)*2);
                uint32_t o01 = (uint32_t)( r0   *ROWB + (k0 + 8 + tig*2)*2);
                uint32_t o11 = (uint32_t)((r0+8)*ROWB + (k0 + 8 + tig*2)*2);
                uint32_t ah0 = *(const uint32_t*)(sAh+o00), ah1 = *(const uint32_t*)(sAh+o10);
                uint32_t ah2 = *(const uint32_t*)(sAh+o01), ah3 = *(const uint32_t*)(sAh+o11);
                uint32_t al0 = *(const uint32_t*)(sAl+o00), al1 = *(const uint32_t*)(sAl+o10);
                uint32_t al2 = *(const uint32_t*)(sAl+o01), al3 = *(const uint32_t*)(sAl+o11);
                #pragma unroll
                for (int nt = 0; nt < 4; nt++){
                    mma16816(acc[mt][nt], ah0, ah1, ah2, ah3, bl[nt][0], bl[nt][1]);
                    mma16816(acc[mt][nt], al0, al1, al2, al3, bh[nt][0], bh[nt][1]);
                    mma16816(acc[mt][nt], ah0, ah1, ah2, ah3, bh[nt][0], bh[nt][1]);
                }
            }
        }
        __syncthreads();
    }

    // epilogue: thread owns rows (g, g+8) of each m-tile, cols (tig*2, +1) of each n-tile
    float sc = (MODE == EPI_RES) ? scale[0] : 0.f;
    #pragma unroll
    for (int mt = 0; mt < 4; mt++){
        #pragma unroll
        for (int half = 0; half < 2; half++){
            int gm = bm + warp_m*64 + mt*16 + g + half*8;
            if (gm >= M) continue;
            #pragma unroll
            for (int nt = 0; nt < 4; nt++){
                int gn = bn + warp_n*32 + nt*8 + tig*2;
                float2 bv = *(const float2*)(bias + gn);
                float vx = acc[mt][nt][half*2+0] + bv.x;
                float vy = acc[mt][nt][half*2+1] + bv.y;
                if (MODE == EPI_GELU){
                    vx = 0.5f*vx*(1.0f + erff(vx*0.7071067811865475f));
                    vy = 0.5f*vy*(1.0f + erff(vy*0.7071067811865475f));
                } else if (MODE == EPI_RES){
                    float2 rv = *(const float2*)(res + (size_t)gm*N + gn);
                    vx = rv.x + sc*vx;
                    vy = rv.y + sc*vy;
                }
                float2 o; o.x = vx; o.y = vy;
                *(float2*)(C + (size_t)gm*N + gn) = o;
            }
        }
    }
}

// ---------------- edge projection ----------------
__global__ void ep_kernel(const float* __restrict__ ef, const float* __restrict__ We,
                          const float* __restrict__ be){
    __shared__ float Ws[EDIM][HDIM+1];
    __shared__ float bs[HDIM];
    int tid = threadIdx.x;
    for (int i = tid; i < EDIM*HDIM; i += blockDim.x){
        int d = i >> 5, j = i & 31;
        Ws[j][d] = We[d*EDIM + j];
    }
    if (tid < HDIM) bs[tid] = be[tid];
    __syncthreads();
    int e = (blockIdx.x*blockDim.x + tid) >> 5;
    if (e >= NE) return;
    int lane = tid & 31;
    float myef = ef[(size_t)e*EDIM + lane];
    float acc = bs[lane];
    #pragma unroll
    for (int j = 0; j < EDIM; j++){
        float efj = __shfl_sync(0xffffffffu, myef, j);
        acc = fmaf(Ws[j][lane], efj, acc);
    }
    g_ep[(size_t)e*HDIM + lane] = acc;
}

// ---------------- attention pass 1: warp per dst node, online softmax ----------------
// software-pipelined: loads for edge j+1 issue during compute of edge j
__global__ void attn1_kernel(const int* __restrict__ src, const float* __restrict__ ew){
    int node = (blockIdx.x*blockDim.x + threadIdx.x) >> 5;
    if (node >= NN) return;
    int lane = threadIdx.x & 31;
    const float* qrow = g_q + (size_t)node*DD;
    float qr[HH];
    #pragma unroll
    for (int h = 0; h < HH; h++) qr[h] = qrow[h*32 + lane];
    float m[HH], l[HH], acc[HH];
    #pragma unroll
    for (int h = 0; h < HH; h++){ m[h] = -INFINITY; l[h] = 0.f; acc[h] = 0.f; }
    int s0 = g_rowptr[node], s1 = g_rowptr[node+1];

    int   e_nx = 0;
    float w_nx = 0.f, ep_nx = 0.f;
    float k_nx[HH], v_nx[HH];
    if (s0 < s1){
        e_nx = g_csr[s0];
        int s = src[e_nx];
        w_nx  = ew[e_nx];
        ep_nx = g_ep[(size_t)e_nx*HDIM + lane];
        const float* kr = g_k + (size_t)s*DD;
        const float* vr = g_v + (size_t)s*DD;
        #pragma unroll
        for (int h = 0; h < HH; h++){ k_nx[h] = kr[h*32 + lane]; v_nx[h] = vr[h*32 + lane]; }
    }

    for (int j = s0; j < s1; j++){
        int   e   = e_nx;
        float w   = w_nx, epl = ep_nx;
        float kc[HH], vc[HH];
        #pragma unroll
        for (int h = 0; h < HH; h++){ kc[h] = k_nx[h]; vc[h] = v_nx[h]; }

        if (j + 1 < s1){
            e_nx = g_csr[j+1];
            int s = src[e_nx];
            w_nx  = ew[e_nx];
            ep_nx = g_ep[(size_t)e_nx*HDIM + lane];
            const float* kr = g_k + (size_t)s*DD;
            const float* vr = g_v + (size_t)s*DD;
            #pragma unroll
            for (int h = 0; h < HH; h++){ k_nx[h] = kr[h*32 + lane]; v_nx[h] = vr[h*32 + lane]; }
        }

        float sc[HH];
        #pragma unroll
        for (int h = 0; h < HH; h++) sc[h] = qr[h] * (kc[h] + epl);
        #pragma unroll
        for (int o = 16; o; o >>= 1){
            #pragma unroll
            for (int h = 0; h < HH; h++) sc[h] += __shfl_xor_sync(0xffffffffu, sc[h], o);
        }
        #pragma unroll
        for (int h = 0; h < HH; h++) sc[h] *= 0.17677669529663688f * w;
        if (lane < HH) g_sc[(size_t)e*HH + lane] = sc[lane];
        #pragma unroll
        for (int h = 0; h < HH; h++){
            float nm = fmaxf(m[h], sc[h]);
            float c  = expf(m[h] - nm);
            float p  = expf(sc[h] - nm);
            l[h]   = l[h]*c + p;
            acc[h] = acc[h]*c + p * vc[h];
            m[h]   = nm;
        }
    }
    float* arow = g_agg + (size_t)node*DD;
    #pragma unroll
    for (int h = 0; h < HH; h++){
        float inv = (l[h] > 0.f) ? 1.f/l[h] : 0.f;
        arow[h*32 + lane] = acc[h] * inv;
    }
    if (lane < HH){ g_m[node*HH + lane] = m[lane]; g_l[node*HH + lane] = l[lane]; }
}

// ---------------- attention pass 2 ----------------
__global__ void attn2_kernel(const int* __restrict__ dst, float* __restrict__ out_attn){
    int i = blockIdx.x*blockDim.x + threadIdx.x;
    if (i >= NE*HH) return;
    int e = i >> 3, h = i & 7;
    int d = dst[e];
    float mm = g_m[d*HH + h];
    float ll = g_l[d*HH + h];
    out_attn[i] = expf(g_sc[i] - mm) / ll;
}

// ---------------- launch ----------------
extern "C" void kernel_launch(void* const* d_in, const int* in_sizes, int n_in,
                              void* d_out, int out_size){
    const float* x   = (const float*)d_in[0];
    const int*   ei  = (const int*)  d_in[1];
    const int*   src = ei;
    const int*   dst = ei + NE;
    const float* ef  = (const float*)d_in[2];
    const float* ew  = (const float*)d_in[3];
    const float* Wq  = (const float*)d_in[4];  const float* bq = (const float*)d_in[5];
    const float* Wk  = (const float*)d_in[6];  const float* bk = (const float*)d_in[7];
    const float* Wv  = (const float*)d_in[8];  const float* bv = (const float*)d_in[9];
    const float* We  = (const float*)d_in[10]; const float* be = (const float*)d_in[11];
    const float* Wo  = (const float*)d_in[12]; const float* bo = (const float*)d_in[13];
    const float* W1  = (const float*)d_in[14]; const float* b1 = (const float*)d_in[15];
    const float* W2  = (const float*)d_in[16]; const float* b2 = (const float*)d_in[17];
    const float* g1  = (const float*)d_in[18]; const float* be1 = (const float*)d_in[19];
    const float* g2  = (const float*)d_in[20]; const float* be2 = (const float*)d_in[21];
    const float* alpha = (const float*)d_in[22];
    const float* beta  = (const float*)d_in[23];

    float* out_x = (float*)d_out;
    float* out_attn = ((size_t)out_size >= (size_t)NN*DD + (size_t)NE*HH)
                      ? out_x + (size_t)NN*DD : nullptr;

    void *p_xn, *p_q, *p_k, *p_v, *p_agg, *p_x1, *p_xn2, *p_ff1;
    cudaGetSymbolAddress(&p_xn,  g_xn);
    cudaGetSymbolAddress(&p_q,   g_q);
    cudaGetSymbolAddress(&p_k,   g_k);
    cudaGetSymbolAddress(&p_v,   g_v);
    cudaGetSymbolAddress(&p_agg, g_agg);
    cudaGetSymbolAddress(&p_x1,  g_x1);
    cudaGetSymbolAddress(&p_xn2, g_xn2);
    cudaGetSymbolAddress(&p_ff1, g_ff1);

    // --- CSR by dst ---
    zero_counts_kernel<<<ceildiv(NN,256), 256>>>();
    hist_kernel<<<ceildiv(NE,256), 256>>>(dst);
    scan_kernel<<<1, 1024>>>();
    scatter_kernel<<<ceildiv(NE,256), 256>>>(dst);

    // --- pre-norm + QKV (3xBF16 warp-MMA) ---
    ln_kernel<<<ceildiv(NN,8), 256>>>(x, g1, be1, (float*)p_xn);
    dim3 gQ(DD/128, ceildiv(NN,128));
    mma_gemm_kernel<EPI_BIAS><<<gQ,256>>>(NN, DD, DD, (const float*)p_xn, Wq, bq, nullptr, nullptr, (float*)p_q);
    mma_gemm_kernel<EPI_BIAS><<<gQ,256>>>(NN, DD, DD, (const float*)p_xn, Wk, bk, nullptr, nullptr, (float*)p_k);
    mma_gemm_kernel<EPI_BIAS><<<gQ,256>>>(NN, DD, DD, (const float*)p_xn, Wv, bv, nullptr, nullptr, (float*)p_v);

    // --- edge projection ---
    ep_kernel<<<ceildiv(NE,8), 256>>>(ef, We, be);

    // --- attention ---
    attn1_kernel<<<ceildiv(NN,8), 256>>>(src, ew);
    if (out_attn)
        attn2_kernel<<<ceildiv(NE*HH,256), 256>>>(dst, out_attn);

    // --- output projection + residual ---
    mma_gemm_kernel<EPI_RES><<<gQ,256>>>(NN, DD, DD, (const float*)p_agg, Wo, bo, x, alpha, (float*)p_x1);

    // --- FFN ---
    ln_kernel<<<ceildiv(NN,8), 256>>>((const float*)p_x1, g2, be2, (float*)p_xn2);
    dim3 gF1(FF/128, ceildiv(NN,128));
    mma_gemm_kernel<EPI_GELU><<<gF1,256>>>(NN, FF, DD, (const float*)p_xn2, W1, b1, nullptr, nullptr, (float*)p_ff1);
    mma_gemm_kernel<EPI_RES><<<gQ,256>>>(NN, DD, FF, (const float*)p_ff1, W2, b2, (const float*)p_x1, beta, out_x);
}

// round 16
// speedup vs baseline: 1.4533x; 1.1584x over previous
#include <cuda_runtime.h>
#include <cuda_bf16.h>
#include <math.h>
#include <stdint.h>

#define NN 50000
#define NE 1600000
#define DD 256
#define HH 8
#define HDIM 32
#define EDIM 32
#define FF 1024

// ---------------- device scratch (static globals; no allocation) ----------------
__device__ float g_xn [(size_t)NN*DD];
__device__ float g_q  [(size_t)NN*DD];
__device__ float g_k  [(size_t)NN*DD];
__device__ float g_v  [(size_t)NN*DD];
__device__ float g_ep [(size_t)NE*HDIM];
__device__ float g_sc [(size_t)NE*HH];
__device__ float g_m  [(size_t)NN*HH];
__device__ float g_l  [(size_t)NN*HH];
__device__ float g_agg[(size_t)NN*DD];
__device__ float g_x1 [(size_t)NN*DD];
__device__ float g_xn2[(size_t)NN*DD];
__device__ float g_ff1[(size_t)NN*FF];
__device__ int   g_counts[NN];
__device__ int   g_rowptr[NN+1];
__device__ int   g_cursor[NN];
__device__ int   g_csr[NE];

static inline int ceildiv(int a, int b){ return (a + b - 1) / b; }

// ---------------- bf16 split helpers ----------------
__device__ __forceinline__ void bf16_split4(float4 v, uint2& hi, uint2& lo){
    __nv_bfloat16 h0 = __float2bfloat16_rn(v.x);
    __nv_bfloat16 h1 = __float2bfloat16_rn(v.y);
    __nv_bfloat16 h2 = __float2bfloat16_rn(v.z);
    __nv_bfloat16 h3 = __float2bfloat16_rn(v.w);
    __nv_bfloat16 l0 = __float2bfloat16_rn(v.x - __bfloat162float(h0));
    __nv_bfloat16 l1 = __float2bfloat16_rn(v.y - __bfloat162float(h1));
    __nv_bfloat16 l2 = __float2bfloat16_rn(v.z - __bfloat162float(h2));
    __nv_bfloat16 l3 = __float2bfloat16_rn(v.w - __bfloat162float(h3));
    hi.x = ((uint32_t)__bfloat16_as_ushort(h1) << 16) | __bfloat16_as_ushort(h0);
    hi.y = ((uint32_t)__bfloat16_as_ushort(h3) << 16) | __bfloat16_as_ushort(h2);
    lo.x = ((uint32_t)__bfloat16_as_ushort(l1) << 16) | __bfloat16_as_ushort(l0);
    lo.y = ((uint32_t)__bfloat16_as_ushort(l3) << 16) | __bfloat16_as_ushort(l2);
}

// mma.sync m16n8k16 row.col f32.bf16.bf16.f32 — base-target PTX (sm_80+)
__device__ __forceinline__ void mma16816(float* c,
        uint32_t a0, uint32_t a1, uint32_t a2, uint32_t a3,
        uint32_t b0, uint32_t b1){
    asm volatile("mma.sync.aligned.m16n8k16.row.col.f32.bf16.bf16.f32 "
        "{%0,%1,%2,%3}, {%4,%5,%6,%7}, {%8,%9}, {%0,%1,%2,%3};"
        : "+f"(c[0]), "+f"(c[1]), "+f"(c[2]), "+f"(c[3])
        : "r"(a0), "r"(a1), "r"(a2), "r"(a3), "r"(b0), "r"(b1));
}

// ldmatrix x4 (base-target PTX, sm_75+)
__device__ __forceinline__ void ldsm4(uint32_t* r, uint32_t saddr){
    asm volatile("ldmatrix.sync.aligned.m8n8.x4.shared.b16 {%0,%1,%2,%3}, [%4];"
        : "=r"(r[0]), "=r"(r[1]), "=r"(r[2]), "=r"(r[3]) : "r"(saddr));
}

// ---------------- CSR build ----------------
__global__ void zero_counts_kernel(){
    int i = blockIdx.x*blockDim.x + threadIdx.x;
    if (i < NN) g_counts[i] = 0;
}
__global__ void hist_kernel(const int* __restrict__ dst){
    int e = blockIdx.x*blockDim.x + threadIdx.x;
    if (e < NE) atomicAdd(&g_counts[dst[e]], 1);
}
__global__ void scan_kernel(){
    __shared__ int sh[2][1024];
    __shared__ int carry;
    int t = threadIdx.x;
    if (t == 0){ carry = 0; g_rowptr[0] = 0; }
    __syncthreads();
    for (int base = 0; base < NN; base += 1024){
        int i = base + t;
        int val = (i < NN) ? g_counts[i] : 0;
        sh[0][t] = val;
        __syncthreads();
        int s = 0, d = 1;
        for (int off = 1; off < 1024; off <<= 1){
            int add = (t >= off) ? sh[s][t-off] : 0;
            sh[d][t] = sh[s][t] + add;
            __syncthreads();
            s ^= 1; d ^= 1;
        }
        int inc = sh[s][t] + carry;
        if (i < NN){ g_rowptr[i+1] = inc; g_cursor[i] = inc - val; }
        __syncthreads();
        if (t == 1023) carry = inc;
        __syncthreads();
    }
}
__global__ void scatter_kernel(const int* __restrict__ dst){
    int e = blockIdx.x*blockDim.x + threadIdx.x;
    if (e >= NE) return;
    int pos = atomicAdd(&g_cursor[dst[e]], 1);
    g_csr[pos] = e;
}

// ---------------- LayerNorm ----------------
__global__ void ln_kernel(const float* __restrict__ x, const float* __restrict__ g,
                          const float* __restrict__ b, float* __restrict__ out){
    int warp = (blockIdx.x*blockDim.x + threadIdx.x) >> 5;
    if (warp >= NN) return;
    int lane = threadIdx.x & 31;
    const float* row = x + (size_t)warp * DD;
    float vals[8];
    #pragma unroll
    for (int j = 0; j < 8; j++) vals[j] = row[j*32 + lane];
    float s = 0.f;
    #pragma unroll
    for (int j = 0; j < 8; j++) s += vals[j];
    #pragma unroll
    for (int o = 16; o; o >>= 1) s += __shfl_xor_sync(0xffffffffu, s, o);
    float mu = s * (1.0f/DD);
    float vs = 0.f;
    #pragma unroll
    for (int j = 0; j < 8; j++){ float d0 = vals[j]-mu; vs += d0*d0; }
    #pragma unroll
    for (int o = 16; o; o >>= 1) vs += __shfl_xor_sync(0xffffffffu, vs, o);
    float rstd = rsqrtf(vs*(1.0f/DD) + 1e-5f);
    float* orow = out + (size_t)warp * DD;
    #pragma unroll
    for (int j = 0; j < 8; j++){
        int c = j*32 + lane;
        orow[c] = (vals[j]-mu)*rstd*g[c] + b[c];
    }
}

// ---------------- 3xBF16 warp-MMA GEMM: C[M,N] = A[M,K] @ B[N,K]^T + bias ----------------
// A = Ah + Al, B = Bh + Bl (bf16 splits). D += Ah@Bh + Ah@Bl + Al@Bh (fp32 accum)
// ldmatrix fragment loads + register-prefetch global pipeline.
#define EPI_BIAS 0
#define EPI_GELU 1
#define EPI_RES  2

#define BKC 32      // K elements per chunk
#define ROWB 80     // padded SMEM row bytes: 32*2 + 16 (bank-conflict-free rows)

template<int MODE>
__global__ __launch_bounds__(256)
void mma_gemm_kernel(int M, int N, int K,
                     const float* __restrict__ A, const float* __restrict__ B,
                     const float* __restrict__ bias,
                     const float* __restrict__ res, const float* __restrict__ scale,
                     float* __restrict__ C){
    __shared__ char sAh[128*ROWB];
    __shared__ char sAl[128*ROWB];
    __shared__ char sBh[128*ROWB];
    __shared__ char sBl[128*ROWB];
    int tid = threadIdx.x;
    int wid = tid >> 5, lane = tid & 31;
    int g = lane >> 2, tig = lane & 3;
    int warp_m = wid & 1, warp_n = wid >> 1;   // 2 x 4 warp grid: warp tile 64 x 32
    int bm = blockIdx.y * 128, bn = blockIdx.x * 128;

    uint32_t baseAh = (uint32_t)__cvta_generic_to_shared(sAh);
    uint32_t baseAl = (uint32_t)__cvta_generic_to_shared(sAl);
    uint32_t baseBh = (uint32_t)__cvta_generic_to_shared(sBh);
    uint32_t baseBl = (uint32_t)__cvta_generic_to_shared(sBl);

    // ldmatrix address components (per lane, constant across chunks)
    int a_row = lane & 15;                     // + r0
    int a_kh  = (lane >> 4) * 8;               // k half
    int b_row = (lane & 7) + ((lane & 16) ? 8 : 0);   // + n0
    int b_kh  = (lane & 8) ? 8 : 0;            // k half

    float acc[4][4][4] = {};   // [mt][nt][c0..c3]

    // register prefetch buffers: 4 float4 of A + 4 of B per thread
    float4 ra[4], rb[4];
    int NC = K / BKC;
    {
        int k0g = 0;
        #pragma unroll
        for (int it = 0; it < 4; it++){
            int idx = tid + it*256;
            int row = idx >> 3, fi = idx & 7;
            int gm = bm + row;
            ra[it] = (gm < M) ? *(const float4*)(A + (size_t)gm*K + k0g + fi*4)
                              : make_float4(0.f,0.f,0.f,0.f);
            rb[it] = *(const float4*)(B + (size_t)(bn + row)*K + k0g + fi*4);
        }
    }

    for (int kc = 0; kc < NC; kc++){
        // store prefetched chunk to smem (hi/lo split)
        #pragma unroll
        for (int it = 0; it < 4; it++){
            int idx = tid + it*256;
            int row = idx >> 3, fi = idx & 7;
            uint32_t off = (uint32_t)(row*ROWB + fi*8);
            uint2 vh, vl;
            bf16_split4(ra[it], vh, vl);
            *(uint2*)(sAh + off) = vh;
            *(uint2*)(sAl + off) = vl;
            bf16_split4(rb[it], vh, vl);
            *(uint2*)(sBh + off) = vh;
            *(uint2*)(sBl + off) = vl;
        }
        __syncthreads();

        // prefetch next chunk (global loads overlap the MMA block below)
        if (kc + 1 < NC){
            int k0g = (kc + 1) * BKC;
            #pragma unroll
            for (int it = 0; it < 4; it++){
                int idx = tid + it*256;
                int row = idx >> 3, fi = idx & 7;
                int gm = bm + row;
                ra[it] = (gm < M) ? *(const float4*)(A + (size_t)gm*K + k0g + fi*4)
                                  : make_float4(0.f,0.f,0.f,0.f);
                rb[it] = *(const float4*)(B + (size_t)(bn + row)*K + k0g + fi*4);
            }
        }

        #pragma unroll
        for (int ks = 0; ks < 2; ks++){
            int k0 = ks*16;
            // B fragments via ldmatrix: 2 blocks of 16 n each
            uint32_t bh[2][4], bl[2][4];
            #pragma unroll
            for (int p = 0; p < 2; p++){
                int n0 = warp_n*32 + p*16;
                uint32_t ba = (uint32_t)((n0 + b_row)*ROWB + (k0 + b_kh)*2);
                ldsm4(bh[p], baseBh + ba);
                ldsm4(bl[p], baseBl + ba);
            }
            #pragma unroll
            for (int mt = 0; mt < 4; mt++){
                int r0 = warp_m*64 + mt*16;
                uint32_t aa = (uint32_t)((r0 + a_row)*ROWB + (k0 + a_kh)*2);
                uint32_t ah[4], al[4];
                ldsm4(ah, baseAh + aa);
                ldsm4(al, baseAl + aa);
                #pragma unroll
                for (int nt = 0; nt < 4; nt++){
                    int p = nt >> 1;
                    int i0 = (nt & 1) * 2;   // even nt: (m0,m1); odd nt: (m2,m3)
                    mma16816(acc[mt][nt], ah[0], ah[1], ah[2], ah[3], bl[p][i0], bl[p][i0+1]);
                    mma16816(acc[mt][nt], al[0], al[1], al[2], al[3], bh[p][i0], bh[p][i0+1]);
                    mma16816(acc[mt][nt], ah[0], ah[1], ah[2], ah[3], bh[p][i0], bh[p][i0+1]);
                }
            }
        }
        __syncthreads();
    }

    // epilogue: thread owns rows (g, g+8) of each m-tile, cols (tig*2, +1) of each n-tile
    float sc = (MODE == EPI_RES) ? scale[0] : 0.f;
    #pragma unroll
    for (int mt = 0; mt < 4; mt++){
        #pragma unroll
        for (int half = 0; half < 2; half++){
            int gm = bm + warp_m*64 + mt*16 + g + half*8;
            if (gm >= M) continue;
            #pragma unroll
            for (int nt = 0; nt < 4; nt++){
                int gn = bn + warp_n*32 + nt*8 + tig*2;
                float2 bv = *(const float2*)(bias + gn);
                float vx = acc[mt][nt][half*2+0] + bv.x;
                float vy = acc[mt][nt][half*2+1] + bv.y;
                if (MODE == EPI_GELU){
                    vx = 0.5f*vx*(1.0f + erff(vx*0.7071067811865475f));
                    vy = 0.5f*vy*(1.0f + erff(vy*0.7071067811865475f));
                } else if (MODE == EPI_RES){
                    float2 rv = *(const float2*)(res + (size_t)gm*N + gn);
                    vx = rv.x + sc*vx;
                    vy = rv.y + sc*vy;
                }
                float2 o; o.x = vx; o.y = vy;
                *(float2*)(C + (size_t)gm*N + gn) = o;
            }
        }
    }
}

// ---------------- edge projection ----------------
__global__ void ep_kernel(const float* __restrict__ ef, const float* __restrict__ We,
                          const float* __restrict__ be){
    __shared__ float Ws[EDIM][HDIM+1];
    __shared__ float bs[HDIM];
    int tid = threadIdx.x;
    for (int i = tid; i < EDIM*HDIM; i += blockDim.x){
        int d = i >> 5, j = i & 31;
        Ws[j][d] = We[d*EDIM + j];
    }
    if (tid < HDIM) bs[tid] = be[tid];
    __syncthreads();
    int e = (blockIdx.x*blockDim.x + tid) >> 5;
    if (e >= NE) return;
    int lane = tid & 31;
    float myef = ef[(size_t)e*EDIM + lane];
    float acc = bs[lane];
    #pragma unroll
    for (int j = 0; j < EDIM; j++){
        float efj = __shfl_sync(0xffffffffu, myef, j);
        acc = fmaf(Ws[j][lane], efj, acc);
    }
    g_ep[(size_t)e*HDIM + lane] = acc;
}

// ---------------- attention pass 1: warp per dst node, online softmax ----------------
// software-pipelined: loads for edge j+1 issue during compute of edge j
__global__ void attn1_kernel(const int* __restrict__ src, const float* __restrict__ ew){
    int node = (blockIdx.x*blockDim.x + threadIdx.x) >> 5;
    if (node >= NN) return;
    int lane = threadIdx.x & 31;
    const float* qrow = g_q + (size_t)node*DD;
    float qr[HH];
    #pragma unroll
    for (int h = 0; h < HH; h++) qr[h] = qrow[h*32 + lane];
    float m[HH], l[HH], acc[HH];
    #pragma unroll
    for (int h = 0; h < HH; h++){ m[h] = -INFINITY; l[h] = 0.f; acc[h] = 0.f; }
    int s0 = g_rowptr[node], s1 = g_rowptr[node+1];

    int   e_nx = 0;
    float w_nx = 0.f, ep_nx = 0.f;
    float k_nx[HH], v_nx[HH];
    if (s0 < s1){
        e_nx = g_csr[s0];
        int s = src[e_nx];
        w_nx  = ew[e_nx];
        ep_nx = g_ep[(size_t)e_nx*HDIM + lane];
        const float* kr = g_k + (size_t)s*DD;
        const float* vr = g_v + (size_t)s*DD;
        #pragma unroll
        for (int h = 0; h < HH; h++){ k_nx[h] = kr[h*32 + lane]; v_nx[h] = vr[h*32 + lane]; }
    }

    for (int j = s0; j < s1; j++){
        int   e   = e_nx;
        float w   = w_nx, epl = ep_nx;
        float kc[HH], vc[HH];
        #pragma unroll
        for (int h = 0; h < HH; h++){ kc[h] = k_nx[h]; vc[h] = v_nx[h]; }

        if (j + 1 < s1){
            e_nx = g_csr[j+1];
            int s = src[e_nx];
            w_nx  = ew[e_nx];
            ep_nx = g_ep[(size_t)e_nx*HDIM + lane];
            const float* kr = g_k + (size_t)s*DD;
            const float* vr = g_v + (size_t)s*DD;
            #pragma unroll
            for (int h = 0; h < HH; h++){ k_nx[h] = kr[h*32 + lane]; v_nx[h] = vr[h*32 + lane]; }
        }

        float sc[HH];
        #pragma unroll
        for (int h = 0; h < HH; h++) sc[h] = qr[h] * (kc[h] + epl);
        #pragma unroll
        for (int o = 16; o; o >>= 1){
            #pragma unroll
            for (int h = 0; h < HH; h++) sc[h] += __shfl_xor_sync(0xffffffffu, sc[h], o);
        }
        #pragma unroll
        for (int h = 0; h < HH; h++) sc[h] *= 0.17677669529663688f * w;
        if (lane < HH) g_sc[(size_t)e*HH + lane] = sc[lane];
        #pragma unroll
        for (int h = 0; h < HH; h++){
            float nm = fmaxf(m[h], sc[h]);
            float c  = expf(m[h] - nm);
            float p  = expf(sc[h] - nm);
            l[h]   = l[h]*c + p;
            acc[h] = acc[h]*c + p * vc[h];
            m[h]   = nm;
        }
    }
    float* arow = g_agg + (size_t)node*DD;
    #pragma unroll
    for (int h = 0; h < HH; h++){
        float inv = (l[h] > 0.f) ? 1.f/l[h] : 0.f;
        arow[h*32 + lane] = acc[h] * inv;
    }
    if (lane < HH){ g_m[node*HH + lane] = m[lane]; g_l[node*HH + lane] = l[lane]; }
}

// ---------------- attention pass 2 ----------------
__global__ void attn2_kernel(const int* __restrict__ dst, float* __restrict__ out_attn){
    int i = blockIdx.x*blockDim.x + threadIdx.x;
    if (i >= NE*HH) return;
    int e = i >> 3, h = i & 7;
    int d = dst[e];
    float mm = g_m[d*HH + h];
    float ll = g_l[d*HH + h];
    out_attn[i] = expf(g_sc[i] - mm) / ll;
}

// ---------------- launch ----------------
extern "C" void kernel_launch(void* const* d_in, const int* in_sizes, int n_in,
                              void* d_out, int out_size){
    const float* x   = (const float*)d_in[0];
    const int*   ei  = (const int*)  d_in[1];
    const int*   src = ei;
    const int*   dst = ei + NE;
    const float* ef  = (const float*)d_in[2];
    const float* ew  = (const float*)d_in[3];
    const float* Wq  = (const float*)d_in[4];  const float* bq = (const float*)d_in[5];
    const float* Wk  = (const float*)d_in[6];  const float* bk = (const float*)d_in[7];
    const float* Wv  = (const float*)d_in[8];  const float* bv = (const float*)d_in[9];
    const float* We  = (const float*)d_in[10]; const float* be = (const float*)d_in[11];
    const float* Wo  = (const float*)d_in[12]; const float* bo = (const float*)d_in[13];
    const float* W1  = (const float*)d_in[14]; const float* b1 = (const float*)d_in[15];
    const float* W2  = (const float*)d_in[16]; const float* b2 = (const float*)d_in[17];
    const float* g1  = (const float*)d_in[18]; const float* be1 = (const float*)d_in[19];
    const float* g2  = (const float*)d_in[20]; const float* be2 = (const float*)d_in[21];
    const float* alpha = (const float*)d_in[22];
    const float* beta  = (const float*)d_in[23];

    float* out_x = (float*)d_out;
    float* out_attn = ((size_t)out_size >= (size_t)NN*DD + (size_t)NE*HH)
                      ? out_x + (size_t)NN*DD : nullptr;

    void *p_xn, *p_q, *p_k, *p_v, *p_agg, *p_x1, *p_xn2, *p_ff1;
    cudaGetSymbolAddress(&p_xn,  g_xn);
    cudaGetSymbolAddress(&p_q,   g_q);
    cudaGetSymbolAddress(&p_k,   g_k);
    cudaGetSymbolAddress(&p_v,   g_v);
    cudaGetSymbolAddress(&p_agg, g_agg);
    cudaGetSymbolAddress(&p_x1,  g_x1);
    cudaGetSymbolAddress(&p_xn2, g_xn2);
    cudaGetSymbolAddress(&p_ff1, g_ff1);

    // --- CSR by dst ---
    zero_counts_kernel<<<ceildiv(NN,256), 256>>>();
    hist_kernel<<<ceildiv(NE,256), 256>>>(dst);
    scan_kernel<<<1, 1024>>>();
    scatter_kernel<<<ceildiv(NE,256), 256>>>(dst);

    // --- pre-norm + QKV (3xBF16 warp-MMA, ldmatrix) ---
    ln_kernel<<<ceildiv(NN,8), 256>>>(x, g1, be1, (float*)p_xn);
    dim3 gQ(DD/128, ceildiv(NN,128));
    mma_gemm_kernel<EPI_BIAS><<<gQ,256>>>(NN, DD, DD, (const float*)p_xn, Wq, bq, nullptr, nullptr, (float*)p_q);
    mma_gemm_kernel<EPI_BIAS><<<gQ,256>>>(NN, DD, DD, (const float*)p_xn, Wk, bk, nullptr, nullptr, (float*)p_k);
    mma_gemm_kernel<EPI_BIAS><<<gQ,256>>>(NN, DD, DD, (const float*)p_xn, Wv, bv, nullptr, nullptr, (float*)p_v);

    // --- edge projection ---
    ep_kernel<<<ceildiv(NE,8), 256>>>(ef, We, be);

    // --- attention ---
    attn1_kernel<<<ceildiv(NN,8), 256>>>(src, ew);
    if (out_attn)
        attn2_kernel<<<ceildiv(NE*HH,256), 256>>>(dst, out_attn);

    // --- output projection + residual ---
    mma_gemm_kernel<EPI_RES><<<gQ,256>>>(NN, DD, DD, (const float*)p_agg, Wo, bo, x, alpha, (float*)p_x1);

    // --- FFN ---
    ln_kernel<<<ceildiv(NN,8), 256>>>((const float*)p_x1, g2, be2, (float*)p_xn2);
    dim3 gF1(FF/128, ceildiv(NN,128));
    mma_gemm_kernel<EPI_GELU><<<gF1,256>>>(NN, FF, DD, (const float*)p_xn2, W1, b1, nullptr, nullptr, (float*)p_ff1);
    mma_gemm_kernel<EPI_RES><<<gQ,256>>>(NN, DD, FF, (const float*)p_ff1, W2, b2, (const float*)p_x1, beta, out_x);
}